// round 12
// baseline (speedup 1.0000x reference)
#include <cuda_runtime.h>
#include <cstdint>

// out[nat, 48] = segment_sum(x*switch, src) - segment_sum(x*switch, dst)
// E = 1.6M, D = 48, nat = 50k.
//
// Certified floor (R4-R11): LTS/L1TEX atomic-f32 path, 38.4M x 16B vector RMW
// ops ~= 106us. This round: persistent grid-stride variant of the R8 winner —
// 148x12 CTAs loop over pair-groups instead of 75k one-shot CTAs, removing
// ~62 wave transitions and the final-wave drain, and giving the compiler a
// loop to software-pipeline next-iteration loads over current reds.

#define D_FEAT 48
#define VECS_PER_EDGE (D_FEAT / 4)   // 12

__device__ __forceinline__ void red_v4(float* p, float a, float b, float c, float d) {
    asm volatile("red.global.add.v4.f32 [%0], {%1,%2,%3,%4};"
                 :: "l"(p), "f"(a), "f"(b), "f"(c), "f"(d) : "memory");
}

__global__ void __launch_bounds__(128)
scatter_edges_kernel(const float4* __restrict__ x4,
                     const float2* __restrict__ sw2,
                     const int2* __restrict__ esrc2,
                     const int2* __restrict__ edst2,
                     float* __restrict__ out,
                     int n_pairs) {
    unsigned total = (unsigned)n_pairs * VECS_PER_EDGE;   // 9.6M for E=1.6M
    unsigned stride = gridDim.x * 128u;

    for (unsigned t = blockIdx.x * 128u + threadIdx.x; t < total; t += stride) {
        unsigned g = t / VECS_PER_EDGE;        // edge pair: edges 2g, 2g+1
        unsigned c = t - g * VECS_PER_EDGE;    // 0..11

        // Paired scalar loads: 1 wavefront each across the 12-lane group
        float2 s  = __ldg(sw2 + g);
        int2  src = __ldg(esrc2 + g);
        int2  dst = __ldg(edst2 + g);

        // Front-load x (streaming; zero reuse)
        unsigned base = g * (2 * VECS_PER_EDGE) + c;
        float4 v0 = __ldcs(x4 + base);
        float4 v1 = __ldcs(x4 + base + VECS_PER_EDGE);

        float ax = v0.x * s.x, ay = v0.y * s.x, az = v0.z * s.x, aw = v0.w * s.x;
        float bx = v1.x * s.y, by = v1.y * s.y, bz = v1.z * s.y, bw = v1.w * s.y;

        unsigned co = c * 4u;
        unsigned o_s0 = (unsigned)src.x * D_FEAT + co;
        unsigned o_d0 = (unsigned)dst.x * D_FEAT + co;
        unsigned o_s1 = (unsigned)src.y * D_FEAT + co;
        unsigned o_d1 = (unsigned)dst.y * D_FEAT + co;

        red_v4(out + o_s0,  ax,  ay,  az,  aw);
        red_v4(out + o_d0, -ax, -ay, -az, -aw);
        red_v4(out + o_s1,  bx,  by,  bz,  bw);
        red_v4(out + o_d1, -bx, -by, -bz, -bw);
    }
}

// Tail for odd edge counts (not hit for E=1.6M).
__global__ void __launch_bounds__(128)
scatter_tail_kernel(const float4* __restrict__ x4,
                    const float* __restrict__ sw,
                    const int* __restrict__ esrc,
                    const int* __restrict__ edst,
                    float* __restrict__ out,
                    int e_start, int n_edges) {
    unsigned t = blockIdx.x * 128u + threadIdx.x;
    unsigned rem = (unsigned)(n_edges - e_start);
    if (t >= rem * VECS_PER_EDGE) return;
    unsigned e = e_start + t / VECS_PER_EDGE;
    unsigned c = t % VECS_PER_EDGE;
    float s = __ldg(sw + e);
    int src = __ldg(esrc + e), dst = __ldg(edst + e);
    float4 v = __ldcs(x4 + (size_t)e * VECS_PER_EDGE + c);
    float ax = v.x * s, ay = v.y * s, az = v.z * s, aw = v.w * s;
    unsigned co = c * 4u;
    red_v4(out + (unsigned)src * D_FEAT + co,  ax,  ay,  az,  aw);
    red_v4(out + (unsigned)dst * D_FEAT + co, -ax, -ay, -az, -aw);
}

extern "C" void kernel_launch(void* const* d_in, const int* in_sizes, int n_in,
                              void* d_out, int out_size) {
    const float4* x4  = (const float4*)d_in[0];   // x [E, 48] fp32
    const float2* sw2 = (const float2*)d_in[1];   // switch [E]
    const int2*   src = (const int2*)d_in[2];     // edge_src [E]
    const int2*   dst = (const int2*)d_in[3];     // edge_dst [E]
    float*        out = (float*)d_out;            // [nat, 48] fp32

    int n_edges = in_sizes[1];
    int n_pairs = n_edges / 2;

    cudaMemsetAsync(out, 0, (size_t)out_size * sizeof(float));

    // Persistent grid: 148 SMs x 12 CTAs of 128 threads (48 warps/SM).
    unsigned total = (unsigned)n_pairs * VECS_PER_EDGE;
    unsigned grid = 148u * 12u;
    unsigned max_grid = (total + 127u) / 128u;
    if (grid > max_grid) grid = max_grid;

    scatter_edges_kernel<<<grid, 128>>>(x4, sw2, src, dst, out, n_pairs);

    if (n_edges & 1) {
        scatter_tail_kernel<<<1, 128>>>((const float4*)d_in[0], (const float*)d_in[1],
                                        (const int*)d_in[2], (const int*)d_in[3],
                                        out, n_edges - 1, n_edges);
    }
}

// round 13
// speedup vs baseline: 1.0911x; 1.0911x over previous
#include <cuda_runtime.h>
#include <cstdint>

// out[nat, 48] = segment_sum(x*switch, src) - segment_sum(x*switch, dst)
// E = 1.6M, D = 48, nat = 50k.
//
// FINAL (certified across R4-R12): this op is bound by the LTS atomic-f32
// datapath — 38.4M x 16B vector RMW ops ~= 1 op/slice/cyc over 184 slices
// ~= 106us, matching measurement within 2%. Exhaustively verified:
//   - REDG.128 tunings (1/2/4 edges per thread, 128/256 blocks)  -> 104-112us
//   - TMA cp.reduce.async.bulk (192B/endpoint)                   -> 108us
//   - dual-engine REDG+TMA split                                 -> 107us
//   - binned gather + atomic hybrid                              -> 139us
//   - persistent grid-stride                                     -> 116us (occ loss)
//   - red.v8: rejected by ptxas (128-bit vector-red ceiling)
//   - PDL prologue overlap: neutral
// Scheme: 12 threads/edge (one float4 each), 2 adjacent edges per thread,
// float2/int2 scalar loads (1 wavefront per 12-lane group), streaming x loads,
// 32-bit offset math, red.global.add.v4.f32 into L2-resident output,
// cudaMemsetAsync zero-init (graph-capturable memset node).

#define D_FEAT 48
#define VECS_PER_EDGE (D_FEAT / 4)   // 12

__device__ __forceinline__ void red_v4(float* p, float a, float b, float c, float d) {
    asm volatile("red.global.add.v4.f32 [%0], {%1,%2,%3,%4};"
                 :: "l"(p), "f"(a), "f"(b), "f"(c), "f"(d) : "memory");
}

__global__ void __launch_bounds__(128)
scatter_edges_kernel(const float4* __restrict__ x4,
                     const float2* __restrict__ sw2,
                     const int2* __restrict__ esrc2,
                     const int2* __restrict__ edst2,
                     float* __restrict__ out,
                     int n_pairs) {
    unsigned t = blockIdx.x * 128u + threadIdx.x;
    unsigned total = (unsigned)n_pairs * VECS_PER_EDGE;
    if (t >= total) return;

    unsigned g = t / VECS_PER_EDGE;        // edge pair: edges 2g, 2g+1
    unsigned c = t - g * VECS_PER_EDGE;    // 0..11

    // Paired scalar loads: 1 wavefront each across the 12-lane group
    float2 s  = __ldg(sw2 + g);
    int2  src = __ldg(esrc2 + g);
    int2  dst = __ldg(edst2 + g);

    // Front-load x (streaming; zero reuse)
    unsigned base = g * (2 * VECS_PER_EDGE) + c;
    float4 v0 = __ldcs(x4 + base);
    float4 v1 = __ldcs(x4 + base + VECS_PER_EDGE);

    float ax = v0.x * s.x, ay = v0.y * s.x, az = v0.z * s.x, aw = v0.w * s.x;
    float bx = v1.x * s.y, by = v1.y * s.y, bz = v1.z * s.y, bw = v1.w * s.y;

    // 32-bit output offsets (max 50k*48 = 2.4M < 2^32)
    unsigned co = c * 4u;
    unsigned o_s0 = (unsigned)src.x * D_FEAT + co;
    unsigned o_d0 = (unsigned)dst.x * D_FEAT + co;
    unsigned o_s1 = (unsigned)src.y * D_FEAT + co;
    unsigned o_d1 = (unsigned)dst.y * D_FEAT + co;

    red_v4(out + o_s0,  ax,  ay,  az,  aw);
    red_v4(out + o_d0, -ax, -ay, -az, -aw);
    red_v4(out + o_s1,  bx,  by,  bz,  bw);
    red_v4(out + o_d1, -bx, -by, -bz, -bw);
}

// Tail for odd edge counts (not hit for E=1.6M).
__global__ void __launch_bounds__(128)
scatter_tail_kernel(const float4* __restrict__ x4,
                    const float* __restrict__ sw,
                    const int* __restrict__ esrc,
                    const int* __restrict__ edst,
                    float* __restrict__ out,
                    int e_start, int n_edges) {
    unsigned t = blockIdx.x * 128u + threadIdx.x;
    unsigned rem = (unsigned)(n_edges - e_start);
    if (t >= rem * VECS_PER_EDGE) return;
    unsigned e = e_start + t / VECS_PER_EDGE;
    unsigned c = t % VECS_PER_EDGE;
    float s = __ldg(sw + e);
    int src = __ldg(esrc + e), dst = __ldg(edst + e);
    float4 v = __ldcs(x4 + (size_t)e * VECS_PER_EDGE + c);
    float ax = v.x * s, ay = v.y * s, az = v.z * s, aw = v.w * s;
    unsigned co = c * 4u;
    red_v4(out + (unsigned)src * D_FEAT + co,  ax,  ay,  az,  aw);
    red_v4(out + (unsigned)dst * D_FEAT + co, -ax, -ay, -az, -aw);
}

extern "C" void kernel_launch(void* const* d_in, const int* in_sizes, int n_in,
                              void* d_out, int out_size) {
    const float4* x4  = (const float4*)d_in[0];   // x [E, 48] fp32
    const float2* sw2 = (const float2*)d_in[1];   // switch [E]
    const int2*   src = (const int2*)d_in[2];     // edge_src [E]
    const int2*   dst = (const int2*)d_in[3];     // edge_dst [E]
    float*        out = (float*)d_out;            // [nat, 48] fp32

    int n_edges = in_sizes[1];
    int n_pairs = n_edges / 2;                    // E = 1.6M -> even

    cudaMemsetAsync(out, 0, (size_t)out_size * sizeof(float));

    unsigned total = (unsigned)n_pairs * VECS_PER_EDGE;
    scatter_edges_kernel<<<(total + 127) / 128, 128>>>(x4, sw2, src, dst, out, n_pairs);

    if (n_edges & 1) {
        scatter_tail_kernel<<<1, 128>>>((const float4*)d_in[0], (const float*)d_in[1],
                                        (const int*)d_in[2], (const int*)d_in[3],
                                        out, n_edges - 1, n_edges);
    }
}

// round 14
// speedup vs baseline: 1.1146x; 1.0215x over previous
#include <cuda_runtime.h>
#include <cstdint>

// out[nat, 48] = segment_sum(x*switch, src) - segment_sum(x*switch, dst)
// E = 1.6M, D = 48, nat = 50k.
//
// FINAL — at the sm_103a LTS atomic-f32 roofline (certified R4-R13):
// 38.4M x 16B vector RMW ops ~= 1 op/LTS-slice/cyc x 184 slices ~= 106us;
// best measured 104.2us kernel / 107.0us end-to-end. Exhausted alternatives:
// REDG tunings (1/2/4 edges/thread), TMA bulk-reduce, dual-engine split,
// binned-gather hybrid, persistent grid, PDL, red.v8 (nonexistent) — all
// equal or worse. Run-to-run noise on this config: +/-2%.
//
// Scheme: 12 threads/edge (one float4 each), 2 adjacent edges per thread,
// float2/int2 scalar loads (1 wavefront per 12-lane group), streaming x
// loads, 32-bit offset math, red.global.add.v4.f32 into L2-resident output,
// cudaMemsetAsync zero-init (graph-capturable memset node).

#define D_FEAT 48
#define VECS_PER_EDGE (D_FEAT / 4)   // 12

__device__ __forceinline__ void red_v4(float* p, float a, float b, float c, float d) {
    asm volatile("red.global.add.v4.f32 [%0], {%1,%2,%3,%4};"
                 :: "l"(p), "f"(a), "f"(b), "f"(c), "f"(d) : "memory");
}

__global__ void __launch_bounds__(128)
scatter_edges_kernel(const float4* __restrict__ x4,
                     const float2* __restrict__ sw2,
                     const int2* __restrict__ esrc2,
                     const int2* __restrict__ edst2,
                     float* __restrict__ out,
                     int n_pairs) {
    unsigned t = blockIdx.x * 128u + threadIdx.x;
    unsigned total = (unsigned)n_pairs * VECS_PER_EDGE;
    if (t >= total) return;

    unsigned g = t / VECS_PER_EDGE;        // edge pair: edges 2g, 2g+1
    unsigned c = t - g * VECS_PER_EDGE;    // 0..11

    // Paired scalar loads: 1 wavefront each across the 12-lane group
    float2 s  = __ldg(sw2 + g);
    int2  src = __ldg(esrc2 + g);
    int2  dst = __ldg(edst2 + g);

    // Front-load x (streaming; zero reuse)
    unsigned base = g * (2 * VECS_PER_EDGE) + c;
    float4 v0 = __ldcs(x4 + base);
    float4 v1 = __ldcs(x4 + base + VECS_PER_EDGE);

    float ax = v0.x * s.x, ay = v0.y * s.x, az = v0.z * s.x, aw = v0.w * s.x;
    float bx = v1.x * s.y, by = v1.y * s.y, bz = v1.z * s.y, bw = v1.w * s.y;

    // 32-bit output offsets (max 50k*48 = 2.4M < 2^32)
    unsigned co = c * 4u;
    unsigned o_s0 = (unsigned)src.x * D_FEAT + co;
    unsigned o_d0 = (unsigned)dst.x * D_FEAT + co;
    unsigned o_s1 = (unsigned)src.y * D_FEAT + co;
    unsigned o_d1 = (unsigned)dst.y * D_FEAT + co;

    red_v4(out + o_s0,  ax,  ay,  az,  aw);
    red_v4(out + o_d0, -ax, -ay, -az, -aw);
    red_v4(out + o_s1,  bx,  by,  bz,  bw);
    red_v4(out + o_d1, -bx, -by, -bz, -bw);
}

// Tail for odd edge counts (not hit for E=1.6M).
__global__ void __launch_bounds__(128)
scatter_tail_kernel(const float4* __restrict__ x4,
                    const float* __restrict__ sw,
                    const int* __restrict__ esrc,
                    const int* __restrict__ edst,
                    float* __restrict__ out,
                    int e_start, int n_edges) {
    unsigned t = blockIdx.x * 128u + threadIdx.x;
    unsigned rem = (unsigned)(n_edges - e_start);
    if (t >= rem * VECS_PER_EDGE) return;
    unsigned e = e_start + t / VECS_PER_EDGE;
    unsigned c = t % VECS_PER_EDGE;
    float s = __ldg(sw + e);
    int src = __ldg(esrc + e), dst = __ldg(edst + e);
    float4 v = __ldcs(x4 + (size_t)e * VECS_PER_EDGE + c);
    float ax = v.x * s, ay = v.y * s, az = v.z * s, aw = v.w * s;
    unsigned co = c * 4u;
    red_v4(out + (unsigned)src * D_FEAT + co,  ax,  ay,  az,  aw);
    red_v4(out + (unsigned)dst * D_FEAT + co, -ax, -ay, -az, -aw);
}

extern "C" void kernel_launch(void* const* d_in, const int* in_sizes, int n_in,
                              void* d_out, int out_size) {
    const float4* x4  = (const float4*)d_in[0];   // x [E, 48] fp32
    const float2* sw2 = (const float2*)d_in[1];   // switch [E]
    const int2*   src = (const int2*)d_in[2];     // edge_src [E]
    const int2*   dst = (const int2*)d_in[3];     // edge_dst [E]
    float*        out = (float*)d_out;            // [nat, 48] fp32

    int n_edges = in_sizes[1];
    int n_pairs = n_edges / 2;                    // E = 1.6M -> even

    cudaMemsetAsync(out, 0, (size_t)out_size * sizeof(float));

    unsigned total = (unsigned)n_pairs * VECS_PER_EDGE;
    scatter_edges_kernel<<<(total + 127) / 128, 128>>>(x4, sw2, src, dst, out, n_pairs);

    if (n_edges & 1) {
        scatter_tail_kernel<<<1, 128>>>((const float4*)d_in[0], (const float*)d_in[1],
                                        (const int*)d_in[2], (const int*)d_in[3],
                                        out, n_edges - 1, n_edges);
    }
}